// round 1
// baseline (speedup 1.0000x reference)
#include <cuda_runtime.h>

// Problem constants
#define HH 32
#define WW 32
#define PP 12
#define BB 4
#define KSTEP 12
#define TE_DEPTH 168
#define NUM_CELLS 1024   // 32*32
#define PQ 24            // P + Q

// Output layout (tuple flattened & concatenated, row-major each):
//  Y       (B,1,H,W,1)       4096   @ 0
//  x       (B,P,H,W,1)      49152   @ 4096
//  trans   (B,P,H,W,8,1)   393216   @ 53248
//  restart (B,P,H,W,1)      49152   @ 446464
//  results (B,P,H,W,1,13)  638976   @ 495616
#define OFF_Y    0
#define OFF_X    4096
#define OFF_T    53248
#define OFF_R    446464
#define OFF_RES  495616

__global__ __launch_bounds__(1024, 1) void rwr_kernel(
    const float* __restrict__ X,
    const int*   __restrict__ TE,
    const float* __restrict__ Wt,   // (1192, 8)
    const float* __restrict__ Wr,   // (1192, 1)
    const float* __restrict__ Wb,   // (1192, 1)
    float*       __restrict__ out)
{
    const int bp   = blockIdx.x;        // 0..47  (b*P + p)
    const int b    = bp / PP;
    const int p    = bp % PP;
    const int cell = threadIdx.x;       // 0..1023
    const int h    = cell >> 5;
    const int w    = cell & 31;

    // Padded shared tiles: trans_prob planes (for w_in gather) + double-buffered x
    __shared__ float tp[8][34][34];     // 36992 B
    __shared__ float xs[2][34][34];     //  9248 B

    // Zero everything (borders must be 0; interior overwritten)
    {
        float* tpf = &tp[0][0][0];
        #pragma unroll
        for (int i = 0; i < 10; i++) {
            int idx = cell + i * 1024;
            if (idx < 8 * 34 * 34) tpf[idx] = 0.0f;
        }
        float* xsf = &xs[0][0][0];
        #pragma unroll
        for (int i = 0; i < 3; i++) {
            int idx = cell + i * 1024;
            if (idx < 2 * 34 * 34) xsf[idx] = 0.0f;
        }
    }

    // ---- one-hot "matmuls" are row lookups ----
    const int te_day  = TE[(b * PQ + p) * 2 + 0];
    const int te_hour = TE[(b * PQ + p) * 2 + 1];
    const int te = te_day * 24 + te_hour;          // < 168
    const int cr = TE_DEPTH + cell;                // cell row in W

    // logits -> softmax over 8 dirs
    float lg[8];
    #pragma unroll
    for (int j = 0; j < 8; j++)
        lg[j] = Wt[te * 8 + j] + Wt[cr * 8 + j];
    float m = lg[0];
    #pragma unroll
    for (int j = 1; j < 8; j++) m = fmaxf(m, lg[j]);
    float e[8], s = 0.0f;
    #pragma unroll
    for (int j = 0; j < 8; j++) { e[j] = expf(lg[j] - m); s += e[j]; }
    const float inv_s = 1.0f / s;
    float tpv[8];
    #pragma unroll
    for (int j = 0; j < 8; j++) tpv[j] = e[j] * inv_s;

    // restart prob (sigmoid) and bias
    const float rz = Wr[te] + Wr[cr];
    const float restart = 1.0f / (1.0f + expf(-rz));
    const float x0 = X[bp * NUM_CELLS + cell];
    const float bias = (Wb[te] + Wb[cr]) * x0;

    // ---- write static outputs ----
    // trans_prob: (..., 8) contiguous per cell -> two float4 stores
    {
        float4* t4 = reinterpret_cast<float4*>(out + OFF_T + (size_t)(bp * NUM_CELLS + cell) * 8);
        t4[0] = make_float4(tpv[0], tpv[1], tpv[2], tpv[3]);
        t4[1] = make_float4(tpv[4], tpv[5], tpv[6], tpv[7]);
    }
    out[OFF_R + bp * NUM_CELLS + cell] = restart;

    // stash trans planes in padded shared for incoming-weight gather
    __syncthreads();   // zero-fill complete before interior writes? (zero pass wrote interior too; ensure ordering)
    #pragma unroll
    for (int j = 0; j < 8; j++) tp[j][h + 1][w + 1] = tpv[j];
    __syncthreads();

    // DIRS (r,c) excluding center, d = index; offset = (r-1, c-1)
    // d : 0:(-1,-1) 1:(-1,0) 2:(-1,1) 3:(0,-1) 4:(0,1) 5:(1,-1) 6:(1,0) 7:(1,1)
    const int DR[8] = {-1,-1,-1, 0, 0, 1, 1, 1};
    const int DC[8] = {-1, 0, 1,-1, 1,-1, 0, 1};

    // incoming weight from neighbor (h+dr, w+dc) via channel d
    float w_in[8];
    #pragma unroll
    for (int d = 0; d < 8; d++)
        w_in[d] = tp[d][h + 1 + DR[d]][w + 1 + DC[d]];

    // ---- iterate ----
    float* res = out + OFF_RES + (size_t)(bp * NUM_CELLS + cell) * (KSTEP + 1);
    float x = x0;
    res[0] = x0;

    const float one_m_r = 1.0f - restart;

    #pragma unroll
    for (int k = 0; k < KSTEP; k++) {
        const int buf = k & 1;
        xs[buf][h + 1][w + 1] = x;
        __syncthreads();
        float xt = 0.0f;
        #pragma unroll
        for (int d = 0; d < 8; d++)
            xt = fmaf(xs[buf][h + 1 + DR[d]][w + 1 + DC[d]], w_in[d], xt);
        x = fmaf(one_m_r, xt, fmaf(restart, x, bias));
        res[k + 1] = x;
    }

    // final state x
    out[OFF_X + bp * NUM_CELLS + cell] = x;
    // Y = x[:, -1:]
    if (p == PP - 1)
        out[OFF_Y + b * NUM_CELLS + cell] = x;
}

extern "C" void kernel_launch(void* const* d_in, const int* in_sizes, int n_in,
                              void* d_out, int out_size) {
    const float* X  = (const float*)d_in[0];
    const int*   TE = (const int*)d_in[1];
    const float* Wt = (const float*)d_in[2];
    const float* Wr = (const float*)d_in[3];
    const float* Wb = (const float*)d_in[4];
    float* out = (float*)d_out;
    rwr_kernel<<<BB * PP, 1024>>>(X, TE, Wt, Wr, Wb, out);
}

// round 2
// speedup vs baseline: 1.3780x; 1.3780x over previous
#include <cuda_runtime.h>

// Problem constants
#define HH 32
#define WW 32
#define PP 12
#define BB 4
#define KSTEP 12
#define TE_DEPTH 168
#define NUM_CELLS 1024   // 32*32
#define PQ 24            // P + Q

// Output layout (tuple flattened & concatenated, row-major each):
//  Y       (B,1,H,W,1)       4096   @ 0
//  x       (B,P,H,W,1)      49152   @ 4096
//  trans   (B,P,H,W,8,1)   393216   @ 53248
//  restart (B,P,H,W,1)      49152   @ 446464
//  results (B,P,H,W,1,13)  638976   @ 495616
#define OFF_Y    0
#define OFF_X    4096
#define OFF_T    53248
#define OFF_R    446464
#define OFF_RES  495616

__global__ __launch_bounds__(1024, 1) void rwr_kernel(
    const float* __restrict__ X,
    const int*   __restrict__ TE,
    const float* __restrict__ Wt,   // (1192, 8)
    const float* __restrict__ Wr,   // (1192, 1)
    const float* __restrict__ Wb,   // (1192, 1)
    float*       __restrict__ out)
{
    const int bp   = blockIdx.x;        // 0..47  (b*P + p)
    const int b    = bp / PP;
    const int p    = bp % PP;
    const int cell = threadIdx.x;       // 0..1023
    const int h    = cell >> 5;
    const int w    = cell & 31;

    // Padded shared tiles: trans_prob planes (for w_in gather) + double-buffered x.
    // tp is reused after the gather phase as the coalescing stage buffer for
    // the results dump (9248 floats >= 512*13 = 6656 floats per half-pass).
    __shared__ __align__(16) float tp[8][34][34];     // 36992 B
    __shared__ __align__(16) float xs[2][34][34];     //  9248 B

    // Zero everything (borders must be 0; interior overwritten)
    {
        float* tpf = &tp[0][0][0];
        #pragma unroll
        for (int i = 0; i < 10; i++) {
            int idx = cell + i * 1024;
            if (idx < 8 * 34 * 34) tpf[idx] = 0.0f;
        }
        float* xsf = &xs[0][0][0];
        #pragma unroll
        for (int i = 0; i < 3; i++) {
            int idx = cell + i * 1024;
            if (idx < 2 * 34 * 34) xsf[idx] = 0.0f;
        }
    }

    // ---- one-hot "matmuls" are row lookups ----
    const int te_day  = TE[(b * PQ + p) * 2 + 0];
    const int te_hour = TE[(b * PQ + p) * 2 + 1];
    const int te = te_day * 24 + te_hour;          // < 168
    const int cr = TE_DEPTH + cell;                // cell row in W

    // logits -> softmax over 8 dirs
    float lg[8];
    #pragma unroll
    for (int j = 0; j < 8; j++)
        lg[j] = Wt[te * 8 + j] + Wt[cr * 8 + j];
    float m = lg[0];
    #pragma unroll
    for (int j = 1; j < 8; j++) m = fmaxf(m, lg[j]);
    float e[8], s = 0.0f;
    #pragma unroll
    for (int j = 0; j < 8; j++) { e[j] = expf(lg[j] - m); s += e[j]; }
    const float inv_s = 1.0f / s;
    float tpv[8];
    #pragma unroll
    for (int j = 0; j < 8; j++) tpv[j] = e[j] * inv_s;

    // restart prob (sigmoid) and bias
    const float rz = Wr[te] + Wr[cr];
    const float restart = 1.0f / (1.0f + expf(-rz));
    const float x0 = X[bp * NUM_CELLS + cell];
    const float bias = (Wb[te] + Wb[cr]) * x0;

    // ---- write static outputs ----
    // trans_prob: (..., 8) contiguous per cell -> two float4 stores
    {
        float4* t4 = reinterpret_cast<float4*>(out + OFF_T + (size_t)(bp * NUM_CELLS + cell) * 8);
        t4[0] = make_float4(tpv[0], tpv[1], tpv[2], tpv[3]);
        t4[1] = make_float4(tpv[4], tpv[5], tpv[6], tpv[7]);
    }
    out[OFF_R + bp * NUM_CELLS + cell] = restart;

    // stash trans planes in padded shared for incoming-weight gather
    __syncthreads();   // zero fill complete
    #pragma unroll
    for (int j = 0; j < 8; j++) tp[j][h + 1][w + 1] = tpv[j];
    __syncthreads();

    // DIRS (r,c) excluding center, d = index; offset = (r-1, c-1)
    const int DR[8] = {-1,-1,-1, 0, 0, 1, 1, 1};
    const int DC[8] = {-1, 0, 1,-1, 1,-1, 0, 1};

    // incoming weight from neighbor (h+dr, w+dc) via channel d
    float w_in[8];
    #pragma unroll
    for (int d = 0; d < 8; d++)
        w_in[d] = tp[d][h + 1 + DR[d]][w + 1 + DC[d]];

    // ---- iterate; keep per-step results in registers ----
    float r[KSTEP + 1];
    float x = x0;
    r[0] = x0;

    const float one_m_r = 1.0f - restart;

    #pragma unroll
    for (int k = 0; k < KSTEP; k++) {
        const int buf = k & 1;
        xs[buf][h + 1][w + 1] = x;
        __syncthreads();
        // balanced fma tree (shorter dep chain than serial 8-fma)
        float a0 = xs[buf][h + 1 + DR[0]][w + 1 + DC[0]] * w_in[0];
        float a1 = xs[buf][h + 1 + DR[1]][w + 1 + DC[1]] * w_in[1];
        float a2 = xs[buf][h + 1 + DR[2]][w + 1 + DC[2]] * w_in[2];
        float a3 = xs[buf][h + 1 + DR[3]][w + 1 + DC[3]] * w_in[3];
        a0 = fmaf(xs[buf][h + 1 + DR[4]][w + 1 + DC[4]], w_in[4], a0);
        a1 = fmaf(xs[buf][h + 1 + DR[5]][w + 1 + DC[5]], w_in[5], a1);
        a2 = fmaf(xs[buf][h + 1 + DR[6]][w + 1 + DC[6]], w_in[6], a2);
        a3 = fmaf(xs[buf][h + 1 + DR[7]][w + 1 + DC[7]], w_in[7], a3);
        float xt = (a0 + a1) + (a2 + a3);
        x = fmaf(one_m_r, xt, fmaf(restart, x, bias));
        r[k + 1] = x;
    }

    // final state x (coalesced)
    out[OFF_X + bp * NUM_CELLS + cell] = x;
    // Y = x[:, -1:]
    if (p == PP - 1)
        out[OFF_Y + b * NUM_CELLS + cell] = x;

    // ---- coalesced results dump: stage through shared (reuse tp), 2 halves ----
    // Half hf covers cells [hf*512, hf*512+512): 512*13 = 6656 floats = 1664 float4.
    float* stage = &tp[0][0][0];
    #pragma unroll
    for (int hf = 0; hf < 2; hf++) {
        __syncthreads();   // prior phase (loop reads / previous half's reads) done
        if ((cell >> 9) == hf) {
            const int lc = cell & 511;
            #pragma unroll
            for (int k = 0; k <= KSTEP; k++)
                stage[lc * 13 + k] = r[k];   // stride 13 (odd) -> conflict-free
        }
        __syncthreads();
        const float4* s4 = reinterpret_cast<const float4*>(stage);
        float4* o4 = reinterpret_cast<float4*>(
            out + OFF_RES + (size_t)bp * (NUM_CELLS * 13) + hf * (512 * 13));
        #pragma unroll
        for (int i = 0; i < 2; i++) {
            int idx = cell + i * 1024;
            if (idx < 1664) o4[idx] = s4[idx];
        }
    }
}

extern "C" void kernel_launch(void* const* d_in, const int* in_sizes, int n_in,
                              void* d_out, int out_size) {
    const float* X  = (const float*)d_in[0];
    const int*   TE = (const int*)d_in[1];
    const float* Wt = (const float*)d_in[2];
    const float* Wr = (const float*)d_in[3];
    const float* Wb = (const float*)d_in[4];
    float* out = (float*)d_out;
    rwr_kernel<<<BB * PP, 1024>>>(X, TE, Wt, Wr, Wb, out);
}